// round 10
// baseline (speedup 1.0000x reference)
#include <cuda_runtime.h>
#include <cuda_bf16.h>
#include <cuda_fp16.h>
#include <cstdint>
#include <cstddef>

#define BB 16
#define NN 2048
#define DD 64
#define SCALE 0.022097086912079608f   // 1/sqrt(2048)
#define NEG_FILL -1000.0f
#define MSPLIT 4
#define NCHUNK 16

// ---------------------------------------------------------------------------
// Scratch (no allocations allowed)
// ---------------------------------------------------------------------------
__device__ __half g_probs[(size_t)BB * NN * NN];   // [b][n][m] = fp16(exp(s))
__device__ float g_crcp[BB * NN];
__device__ float g_psum[NCHUNK * BB * NN];
__device__ float g_pout[(size_t)MSPLIT * BB * NN * DD];
__device__ __align__(16) __nv_bfloat16 g_qh[(size_t)BB * NN * DD];
__device__ __align__(16) __nv_bfloat16 g_ql[(size_t)BB * NN * DD];
__device__ __align__(16) __nv_bfloat16 g_kh[(size_t)BB * NN * DD];
__device__ __align__(16) __nv_bfloat16 g_kl[(size_t)BB * NN * DD];

// ---------------------------------------------------------------------------
// Helpers
// ---------------------------------------------------------------------------
__device__ __forceinline__ uint32_t smem_u32(const void* p) {
    uint32_t a;
    asm("{ .reg .u64 t; cvta.to.shared.u64 t, %1; cvt.u32.u64 %0, t; }"
        : "=r"(a) : "l"(p));
    return a;
}

#define LDSM4(r, a)                                                            \
    asm volatile("ldmatrix.sync.aligned.m8n8.x4.shared.b16 {%0,%1,%2,%3}, [%4];" \
        : "=r"((r)[0]), "=r"((r)[1]), "=r"((r)[2]), "=r"((r)[3]) : "r"(a))
#define LDSM4T(r, a)                                                           \
    asm volatile("ldmatrix.sync.aligned.m8n8.x4.trans.shared.b16 {%0,%1,%2,%3}, [%4];" \
        : "=r"((r)[0]), "=r"((r)[1]), "=r"((r)[2]), "=r"((r)[3]) : "r"(a))
#define MMA_BF16(c, a, b)                                                      \
    asm volatile("mma.sync.aligned.m16n8k16.row.col.f32.bf16.bf16.f32 "        \
        "{%0,%1,%2,%3}, {%4,%5,%6,%7}, {%8,%9}, {%0,%1,%2,%3};"                \
        : "+f"((c)[0]), "+f"((c)[1]), "+f"((c)[2]), "+f"((c)[3])               \
        : "r"((a)[0]), "r"((a)[1]), "r"((a)[2]), "r"((a)[3]),                  \
          "r"((b)[0]), "r"((b)[1]))

__device__ __forceinline__ void split2(float x, float y, uint32_t& hi, uint32_t& lo) {
    __nv_bfloat16 hx = __float2bfloat16(x), hy = __float2bfloat16(y);
    __nv_bfloat16 lx = __float2bfloat16(x - __bfloat162float(hx));
    __nv_bfloat16 ly = __float2bfloat16(y - __bfloat162float(hy));
    hi = (uint32_t)__bfloat16_as_ushort(hx) | ((uint32_t)__bfloat16_as_ushort(hy) << 16);
    lo = (uint32_t)__bfloat16_as_ushort(lx) | ((uint32_t)__bfloat16_as_ushort(ly) << 16);
}

// ============================================================================
// Kernel 0: split q, k into bf16 hi/lo
// ============================================================================
__global__ void prep_kernel(const float* __restrict__ q,
                            const float* __restrict__ k) {
    int i = blockIdx.x * 256 + threadIdx.x;     // float4 index, 524288 total
    float4 vq = ((const float4*)q)[i];
    float4 vk = ((const float4*)k)[i];
    uint32_t h0, h1, l0, l1;
    split2(vq.x, vq.y, h0, l0); split2(vq.z, vq.w, h1, l1);
    ((uint2*)g_qh)[i] = make_uint2(h0, h1);
    ((uint2*)g_ql)[i] = make_uint2(l0, l1);
    split2(vk.x, vk.y, h0, l0); split2(vk.z, vk.w, h1, l1);
    ((uint2*)g_kh)[i] = make_uint2(h0, h1);
    ((uint2*)g_kl)[i] = make_uint2(l0, l1);
}

// ============================================================================
// Kernel 1: probs via HMMA + fused per-column partial sums (max-free).
// Block 128(n) x 128(m); 8 warps in 2(n) x 4(m); warp tile 64x32.
// Stores fp16 p = exp(masked scaled score); accumulates column sums of the
// ROUNDED p for exact softmax self-consistency.
// ============================================================================
#define SC_SMEM 65536

__global__ void __launch_bounds__(256, 2)
scores_mma_kernel(const int* __restrict__ mask) {
    extern __shared__ char smc[];
    const uint32_t sb = smem_u32(smc);
    const int t = threadIdx.x, l = t & 31, wid = t >> 5;
    const int m0 = blockIdx.x * 128, n0 = blockIdx.y * 128, b = blockIdx.z;
    const int nb = blockIdx.y;
    const int wn = wid >> 2, wm = wid & 3;

    const uint32_t QH = 0, QL = 16384, KH = 32768, KL = 49152;

    {
        const uint4* qh = (const uint4*)(g_qh + ((size_t)b * NN + n0) * DD);
        const uint4* ql = (const uint4*)(g_ql + ((size_t)b * NN + n0) * DD);
        const uint4* kh = (const uint4*)(g_kh + ((size_t)b * NN + m0) * DD);
        const uint4* kl = (const uint4*)(g_kl + ((size_t)b * NN + m0) * DD);
#pragma unroll
        for (int i = 0; i < 4; i++) {
            int idx = i * 256 + t;
            int row = idx >> 3, q = idx & 7;
            uint32_t off = (uint32_t)(row * 128 + ((q ^ (row & 7)) << 4));
            *(uint4*)(smc + QH + off) = qh[idx];
            *(uint4*)(smc + QL + off) = ql[idx];
            *(uint4*)(smc + KH + off) = kh[idx];
            *(uint4*)(smc + KL + off) = kl[idx];
        }
    }
    __syncthreads();

    float c[4][4][4];
#pragma unroll
    for (int i = 0; i < 4; i++)
#pragma unroll
        for (int j = 0; j < 4; j++)
#pragma unroll
            for (int r = 0; r < 4; r++) c[i][j][r] = 0.f;

#pragma unroll
    for (int pass = 0; pass < 3; pass++) {
        const uint32_t Ab = sb + ((pass == 2) ? QL : QH);
        const uint32_t Bb = sb + ((pass == 1) ? KL : KH);
#pragma unroll
        for (int ks = 0; ks < 4; ks++) {
            uint32_t a[4][4], bf[2][4];
#pragma unroll
            for (int fn = 0; fn < 4; fn++) {
                int row = wn * 64 + fn * 16 + (l & 15);
                int blk = ks * 2 + (l >> 4);
                LDSM4(a[fn], Ab + row * 128 + ((blk ^ (row & 7)) << 4));
            }
#pragma unroll
            for (int p = 0; p < 2; p++) {
                int row = wm * 32 + p * 16 + ((l >> 4) << 3) + (l & 7);
                int blk = ks * 2 + ((l >> 3) & 1);
                LDSM4(bf[p], Bb + row * 128 + ((blk ^ (row & 7)) << 4));
            }
#pragma unroll
            for (int fn = 0; fn < 4; fn++)
#pragma unroll
                for (int fm = 0; fm < 4; fm++)
                    MMA_BF16(c[fn][fm], a[fn], &bf[fm >> 1][(fm & 1) * 2]);
        }
    }

    // Epilogue: p = mask ? 0 : exp(s*SCALE); store fp16; keep rounded p in c
    const int g = l >> 2, tig = l & 3;
#pragma unroll
    for (int fn = 0; fn < 4; fn++) {
#pragma unroll
        for (int h = 0; h < 2; h++) {
            int n = n0 + wn * 64 + fn * 16 + g + h * 8;
#pragma unroll
            for (int fm = 0; fm < 4; fm++) {
                int m = m0 + wm * 32 + fm * 8 + tig * 2;
                size_t addr = ((size_t)b * NN + n) * NN + m;
                int2 mk = *(const int2*)(mask + addr);
                float x = mk.x ? 0.f : __expf(c[fn][fm][h * 2] * SCALE);
                float y = mk.y ? 0.f : __expf(c[fn][fm][h * 2 + 1] * SCALE);
                __half2 hh = __floats2half2_rn(x, y);
                *(__half2*)(g_probs + addr) = hh;
                c[fn][fm][h * 2]     = __half2float(__low2half(hh));
                c[fn][fm][h * 2 + 1] = __half2float(__high2half(hh));
            }
        }
    }

    // Per-thread column sums: 8 columns (fm x e), 8 rows each (fn x h)
    float cs[4][2];
#pragma unroll
    for (int fm = 0; fm < 4; fm++) { cs[fm][0] = 0.f; cs[fm][1] = 0.f; }
#pragma unroll
    for (int fn = 0; fn < 4; fn++)
#pragma unroll
        for (int h = 0; h < 2; h++)
#pragma unroll
            for (int fm = 0; fm < 4; fm++) {
                cs[fm][0] += c[fn][fm][h * 2];
                cs[fm][1] += c[fn][fm][h * 2 + 1];
            }
    // Butterfly sum over g lanes (stride 4, 8, 16)
#pragma unroll
    for (int st = 4; st <= 16; st <<= 1)
#pragma unroll
        for (int fm = 0; fm < 4; fm++)
#pragma unroll
            for (int e = 0; e < 2; e++)
                cs[fm][e] += __shfl_xor_sync(0xFFFFFFFFu, cs[fm][e], st);

    // Combine the two n-warps via smem (reuse tile region)
    __syncthreads();
    float* sms = (float*)smc;          // [2][128]
    if (l < 4) {
#pragma unroll
        for (int fm = 0; fm < 4; fm++)
#pragma unroll
            for (int e = 0; e < 2; e++) {
                int ml = wm * 32 + fm * 8 + l * 2 + e;
                sms[wn * 128 + ml] = cs[fm][e];
            }
    }
    __syncthreads();
    if (t < 128)
        g_psum[(nb * BB + b) * NN + m0 + t] = sms[t] + sms[128 + t];
}

// ============================================================================
// Kernel 2: combine NCHUNK partial sums -> g_crcp
// ============================================================================
__global__ void colstats2_kernel() {
    const int m = blockIdx.x * 256 + threadIdx.x;
    const int b = blockIdx.y;
    float S = 0.f;
#pragma unroll
    for (int i = 0; i < NCHUNK; i++) S += g_psum[(i * BB + b) * NN + m];
    g_crcp[b * NN + m] = 1.f / S;
}

// ============================================================================
// Kernel 3: partial out = P·V' via HMMA over an m-range of NN/MSPLIT,
// V'[m][d] = rcp[m]*v[m][d]. Block 128(n) x 64(d); k-chunks of 64 m.
// grid (NN/128, BB, MSPLIT). P read as fp16 (exact bf16 hi/lo split).
// ============================================================================
#define O_PH 0
#define O_PL 16384
#define O_VH 32768
#define O_VL 40960
#define O_CR 49152
#define O_SMEM 49408

__global__ void __launch_bounds__(256, 2)
out_mma_kernel(const float* __restrict__ v) {
    extern __shared__ char smc[];
    const uint32_t sb = smem_u32(smc);
    float* scr = (float*)(smc + O_CR);
    const int t = threadIdx.x, l = t & 31, wid = t >> 5;
    const int nblk = blockIdx.x * 128, b = blockIdx.y, z = blockIdx.z;
    const int wn = wid >> 1, wd = wid & 1;

    float c[2][4][4];
#pragma unroll
    for (int i = 0; i < 2; i++)
#pragma unroll
        for (int j = 0; j < 4; j++)
#pragma unroll
            for (int r = 0; r < 4; r++) c[i][j][r] = 0.f;

    const int ck0 = z * (NN / MSPLIT / 64);
    for (int ci = 0; ci < NN / MSPLIT / 64; ci++) {
        const int m0c = (ck0 + ci) * 64;
        __syncthreads();
        if (t < 64) scr[t] = g_crcp[b * NN + m0c + t];
        __syncthreads();

        // Stage P (128n x 64m): fp16 load, exact hi/lo split, swizzled
        const __half* sg = g_probs + ((size_t)b * NN + nblk) * NN + m0c;
#pragma unroll
        for (int i = 0; i < 4; i++) {
            int idx = i * 256 + t;
            int row = idx >> 3, c8 = idx & 7;
            uint4 raw = *(const uint4*)(sg + (size_t)row * NN + c8 * 8);
            const __half2* hp = (const __half2*)&raw;
            uint32_t hv[4], lv[4];
#pragma unroll
            for (int p = 0; p < 4; p++) {
                float2 sf = __half22float2(hp[p]);
                split2(sf.x, sf.y, hv[p], lv[p]);
            }
            uint32_t off = (uint32_t)(row * 128 + ((c8 ^ (row & 7)) << 4));
            *(uint4*)(smc + O_PH + off) = make_uint4(hv[0], hv[1], hv[2], hv[3]);
            *(uint4*)(smc + O_PL + off) = make_uint4(lv[0], lv[1], lv[2], lv[3]);
        }
        // Stage V' (64m x 64d): rcp-prescale + hi/lo split, swizzled
        const float* vg = v + ((size_t)b * NN + m0c) * DD;
#pragma unroll
        for (int i = 0; i < 4; i++) {
            int idx = i * 256 + t;
            int row = idx >> 4, c4 = idx & 15;
            float4 v4 = *(const float4*)(vg + (size_t)row * DD + c4 * 4);
            float rs = scr[row];
            v4.x *= rs; v4.y *= rs; v4.z *= rs; v4.w *= rs;
            uint32_t h01, l01, h23, l23;
            split2(v4.x, v4.y, h01, l01);
            split2(v4.z, v4.w, h23, l23);
            uint32_t off = (uint32_t)(row * 128 + (((c4 >> 1) ^ (row & 7)) << 4) +
                                      ((c4 & 1) << 3));
            *(uint2*)(smc + O_VH + off) = make_uint2(h01, h23);
            *(uint2*)(smc + O_VL + off) = make_uint2(l01, l23);
        }
        __syncthreads();

#pragma unroll
        for (int pass = 0; pass < 3; pass++) {
            const uint32_t Ab = sb + ((pass == 2) ? O_PL : O_PH);
            const uint32_t Bb = sb + ((pass == 1) ? O_VL : O_VH);
#pragma unroll
            for (int ks = 0; ks < 4; ks++) {
                uint32_t a[2][4], bf[2][4];
#pragma unroll
                for (int fn = 0; fn < 2; fn++) {
                    int row = wn * 32 + fn * 16 + (l & 15);
                    int blk = ks * 2 + (l >> 4);
                    LDSM4(a[fn], Ab + row * 128 + ((blk ^ (row & 7)) << 4));
                }
#pragma unroll
                for (int p = 0; p < 2; p++) {
                    int row = ks * 16 + ((l >> 3) & 1) * 8 + (l & 7);
                    int blk = wd * 4 + p * 2 + (l >> 4);
                    LDSM4T(bf[p], Bb + row * 128 + ((blk ^ (row & 7)) << 4));
                }
#pragma unroll
                for (int fn = 0; fn < 2; fn++)
#pragma unroll
                    for (int fb = 0; fb < 4; fb++)
                        MMA_BF16(c[fn][fb], a[fn], &bf[fb >> 1][(fb & 1) * 2]);
            }
        }
    }

    float* po = g_pout + (size_t)z * BB * NN * DD;
    const int g = l >> 2, tig = l & 3;
#pragma unroll
    for (int fn = 0; fn < 2; fn++) {
#pragma unroll
        for (int h = 0; h < 2; h++) {
            int n = nblk + wn * 32 + fn * 16 + g + h * 8;
#pragma unroll
            for (int fb = 0; fb < 4; fb++) {
                int d = wd * 32 + fb * 8 + tig * 2;
                float2 o = make_float2(c[fn][fb][h * 2], c[fn][fb][h * 2 + 1]);
                *(float2*)(po + ((size_t)b * NN + n) * DD + d) = o;
            }
        }
    }
}

// ============================================================================
// Kernel 4: reduce MSPLIT partials -> out (deterministic order)
// ============================================================================
__global__ void reduce_kernel(float* __restrict__ out) {
    size_t i = (size_t)blockIdx.x * 256 + threadIdx.x;   // float4 index
    const size_t stride = (size_t)BB * NN * DD / 4;
    float4 a = ((const float4*)g_pout)[i];
#pragma unroll
    for (int z = 1; z < MSPLIT; z++) {
        float4 p = ((const float4*)g_pout)[z * stride + i];
        a.x += p.x; a.y += p.y; a.z += p.z; a.w += p.w;
    }
    ((float4*)out)[i] = a;
}

// ============================================================================
extern "C" void kernel_launch(void* const* d_in, const int* in_sizes, int n_in,
                              void* d_out, int out_size) {
    const float* q = (const float*)d_in[0];
    const float* k = (const float*)d_in[1];
    const float* v = (const float*)d_in[2];
    const int* mask = (const int*)d_in[3];
    float* out = (float*)d_out;

    cudaFuncSetAttribute(scores_mma_kernel,
                         cudaFuncAttributeMaxDynamicSharedMemorySize, SC_SMEM);
    cudaFuncSetAttribute(out_mma_kernel,
                         cudaFuncAttributeMaxDynamicSharedMemorySize, O_SMEM);

    prep_kernel<<<2048, 256>>>(q, k);
    scores_mma_kernel<<<dim3(NN / 128, NN / 128, BB), 256, SC_SMEM>>>(mask);
    colstats2_kernel<<<dim3(NN / 256, BB), 256>>>();
    out_mma_kernel<<<dim3(NN / 128, BB, MSPLIT), 256, O_SMEM>>>(v);
    reduce_kernel<<<BB * NN * DD / 4 / 256, 256>>>(out);
}

// round 15
// speedup vs baseline: 1.3726x; 1.3726x over previous
#include <cuda_runtime.h>
#include <cuda_fp16.h>
#include <cstdint>
#include <cstddef>

#define BB 16
#define NN 2048
#define DD 64
#define SCALE 0.022097086912079608f   // 1/sqrt(2048)
#define MSPLIT 4
#define NCHUNK 16

// ---------------------------------------------------------------------------
// Scratch (no allocations allowed)
// ---------------------------------------------------------------------------
__device__ __half g_probs[(size_t)BB * NN * NN];   // [b][n][m] = fp16(exp(s))
__device__ float g_crcp[BB * NN];
__device__ float g_psum[NCHUNK * BB * NN];
__device__ float g_pout[(size_t)MSPLIT * BB * NN * DD];
__device__ __align__(16) __half g_qf[(size_t)BB * NN * DD];
__device__ __align__(16) __half g_kf[(size_t)BB * NN * DD];

// ---------------------------------------------------------------------------
// Helpers
// ---------------------------------------------------------------------------
__device__ __forceinline__ uint32_t smem_u32(const void* p) {
    uint32_t a;
    asm("{ .reg .u64 t; cvta.to.shared.u64 t, %1; cvt.u32.u64 %0, t; }"
        : "=r"(a) : "l"(p));
    return a;
}

__device__ __forceinline__ uint32_t pack_h2(__half2 h) {
    uint32_t u;
    u = (uint32_t)__half_as_ushort(__low2half(h)) |
        ((uint32_t)__half_as_ushort(__high2half(h)) << 16);
    return u;
}

#define LDSM4(r, a)                                                            \
    asm volatile("ldmatrix.sync.aligned.m8n8.x4.shared.b16 {%0,%1,%2,%3}, [%4];" \
        : "=r"((r)[0]), "=r"((r)[1]), "=r"((r)[2]), "=r"((r)[3]) : "r"(a))
#define LDSM4T(r, a)                                                           \
    asm volatile("ldmatrix.sync.aligned.m8n8.x4.trans.shared.b16 {%0,%1,%2,%3}, [%4];" \
        : "=r"((r)[0]), "=r"((r)[1]), "=r"((r)[2]), "=r"((r)[3]) : "r"(a))
#define MMA_F16(c, a, b)                                                       \
    asm volatile("mma.sync.aligned.m16n8k16.row.col.f32.f16.f16.f32 "          \
        "{%0,%1,%2,%3}, {%4,%5,%6,%7}, {%8,%9}, {%0,%1,%2,%3};"                \
        : "+f"((c)[0]), "+f"((c)[1]), "+f"((c)[2]), "+f"((c)[3])               \
        : "r"((a)[0]), "r"((a)[1]), "r"((a)[2]), "r"((a)[3]),                  \
          "r"((b)[0]), "r"((b)[1]))

// fp16 hi/lo split (22 effective mantissa bits across the pair)
__device__ __forceinline__ void split2h(float x, float y, uint32_t& hi, uint32_t& lo) {
    __half hx = __float2half_rn(x), hy = __float2half_rn(y);
    __half lx = __float2half_rn(x - __half2float(hx));
    __half ly = __float2half_rn(y - __half2float(hy));
    hi = (uint32_t)__half_as_ushort(hx) | ((uint32_t)__half_as_ushort(hy) << 16);
    lo = (uint32_t)__half_as_ushort(lx) | ((uint32_t)__half_as_ushort(ly) << 16);
}

// ============================================================================
// Kernel 0: round q, k to fp16
// ============================================================================
__global__ void prep_kernel(const float* __restrict__ q,
                            const float* __restrict__ k) {
    int i = blockIdx.x * 256 + threadIdx.x;     // float4 index, 524288 total
    float4 vq = ((const float4*)q)[i];
    float4 vk = ((const float4*)k)[i];
    uint32_t q01 = pack_h2(__floats2half2_rn(vq.x, vq.y));
    uint32_t q23 = pack_h2(__floats2half2_rn(vq.z, vq.w));
    uint32_t k01 = pack_h2(__floats2half2_rn(vk.x, vk.y));
    uint32_t k23 = pack_h2(__floats2half2_rn(vk.z, vk.w));
    ((uint2*)g_qf)[i] = make_uint2(q01, q23);
    ((uint2*)g_kf)[i] = make_uint2(k01, k23);
}

// ============================================================================
// Kernel 1: probs via single-pass fp16 HMMA + fused column partial sums.
// Block 128(n) x 128(m); 8 warps in 2(n) x 4(m); warp tile 64x32.
// ============================================================================
#define SC_SMEM 32768

__global__ void __launch_bounds__(256, 2)
scores_mma_kernel(const int* __restrict__ mask) {
    extern __shared__ char smc[];
    const uint32_t sb = smem_u32(smc);
    const int t = threadIdx.x, l = t & 31, wid = t >> 5;
    const int m0 = blockIdx.x * 128, n0 = blockIdx.y * 128, b = blockIdx.z;
    const int nb = blockIdx.y;
    const int wn = wid >> 2, wm = wid & 3;

    const uint32_t QF = 0, KF = 16384;

    {
        const uint4* qf = (const uint4*)(g_qf + ((size_t)b * NN + n0) * DD);
        const uint4* kf = (const uint4*)(g_kf + ((size_t)b * NN + m0) * DD);
#pragma unroll
        for (int i = 0; i < 4; i++) {
            int idx = i * 256 + t;
            int row = idx >> 3, q = idx & 7;
            uint32_t off = (uint32_t)(row * 128 + ((q ^ (row & 7)) << 4));
            *(uint4*)(smc + QF + off) = qf[idx];
            *(uint4*)(smc + KF + off) = kf[idx];
        }
    }
    __syncthreads();

    float c[4][4][4];
#pragma unroll
    for (int i = 0; i < 4; i++)
#pragma unroll
        for (int j = 0; j < 4; j++)
#pragma unroll
            for (int r = 0; r < 4; r++) c[i][j][r] = 0.f;

#pragma unroll
    for (int ks = 0; ks < 4; ks++) {
        uint32_t a[4][4], bf[2][4];
#pragma unroll
        for (int fn = 0; fn < 4; fn++) {
            int row = wn * 64 + fn * 16 + (l & 15);
            int blk = ks * 2 + (l >> 4);
            LDSM4(a[fn], sb + QF + row * 128 + ((blk ^ (row & 7)) << 4));
        }
#pragma unroll
        for (int p = 0; p < 2; p++) {
            int row = wm * 32 + p * 16 + ((l >> 4) << 3) + (l & 7);
            int blk = ks * 2 + ((l >> 3) & 1);
            LDSM4(bf[p], sb + KF + row * 128 + ((blk ^ (row & 7)) << 4));
        }
#pragma unroll
        for (int fn = 0; fn < 4; fn++)
#pragma unroll
            for (int fm = 0; fm < 4; fm++)
                MMA_F16(c[fn][fm], a[fn], &bf[fm >> 1][(fm & 1) * 2]);
    }

    // Epilogue: p = mask ? 0 : exp(s*SCALE); store fp16; keep rounded p in c
    const int g = l >> 2, tig = l & 3;
#pragma unroll
    for (int fn = 0; fn < 4; fn++) {
#pragma unroll
        for (int h = 0; h < 2; h++) {
            int n = n0 + wn * 64 + fn * 16 + g + h * 8;
#pragma unroll
            for (int fm = 0; fm < 4; fm++) {
                int m = m0 + wm * 32 + fm * 8 + tig * 2;
                size_t addr = ((size_t)b * NN + n) * NN + m;
                int2 mk = *(const int2*)(mask + addr);
                float x = mk.x ? 0.f : __expf(c[fn][fm][h * 2] * SCALE);
                float y = mk.y ? 0.f : __expf(c[fn][fm][h * 2 + 1] * SCALE);
                __half2 hh = __floats2half2_rn(x, y);
                *(__half2*)(g_probs + addr) = hh;
                c[fn][fm][h * 2]     = __half2float(__low2half(hh));
                c[fn][fm][h * 2 + 1] = __half2float(__high2half(hh));
            }
        }
    }

    // Per-thread column sums: 8 columns (fm x e), 8 rows each (fn x h)
    float cs[4][2];
#pragma unroll
    for (int fm = 0; fm < 4; fm++) { cs[fm][0] = 0.f; cs[fm][1] = 0.f; }
#pragma unroll
    for (int fn = 0; fn < 4; fn++)
#pragma unroll
        for (int h = 0; h < 2; h++)
#pragma unroll
            for (int fm = 0; fm < 4; fm++) {
                cs[fm][0] += c[fn][fm][h * 2];
                cs[fm][1] += c[fn][fm][h * 2 + 1];
            }
#pragma unroll
    for (int st = 4; st <= 16; st <<= 1)
#pragma unroll
        for (int fm = 0; fm < 4; fm++)
#pragma unroll
            for (int e = 0; e < 2; e++)
                cs[fm][e] += __shfl_xor_sync(0xFFFFFFFFu, cs[fm][e], st);

    __syncthreads();
    float* sms = (float*)smc;          // [2][128]
    if (l < 4) {
#pragma unroll
        for (int fm = 0; fm < 4; fm++)
#pragma unroll
            for (int e = 0; e < 2; e++) {
                int ml = wm * 32 + fm * 8 + l * 2 + e;
                sms[wn * 128 + ml] = cs[fm][e];
            }
    }
    __syncthreads();
    if (t < 128)
        g_psum[(nb * BB + b) * NN + m0 + t] = sms[t] + sms[128 + t];
}

// ============================================================================
// Kernel 2: combine NCHUNK partial sums -> g_crcp
// ============================================================================
__global__ void colstats2_kernel() {
    const int m = blockIdx.x * 256 + threadIdx.x;
    const int b = blockIdx.y;
    float S = 0.f;
#pragma unroll
    for (int i = 0; i < NCHUNK; i++) S += g_psum[(i * BB + b) * NN + m];
    g_crcp[b * NN + m] = 1.f / S;
}

// ============================================================================
// Kernel 3: partial out = P·V' via 2-pass fp16 HMMA over an m-range,
// V'[m][d] = rcp[m]*v[m][d] split fp16 hi/lo; P fp16 exact (pure copy stage).
// Block 128(n) x 64(d); k-chunks of 64 m. grid (NN/128, BB, MSPLIT).
// ============================================================================
#define O_P  0
#define O_VH 16384
#define O_VL 24576
#define O_CR 32768
#define O_SMEM 33024

__global__ void __launch_bounds__(256, 2)
out_mma_kernel(const float* __restrict__ v) {
    extern __shared__ char smc[];
    const uint32_t sb = smem_u32(smc);
    float* scr = (float*)(smc + O_CR);
    const int t = threadIdx.x, l = t & 31, wid = t >> 5;
    const int nblk = blockIdx.x * 128, b = blockIdx.y, z = blockIdx.z;
    const int wn = wid >> 1, wd = wid & 1;

    float c[2][4][4];
#pragma unroll
    for (int i = 0; i < 2; i++)
#pragma unroll
        for (int j = 0; j < 4; j++)
#pragma unroll
            for (int r = 0; r < 4; r++) c[i][j][r] = 0.f;

    const int ck0 = z * (NN / MSPLIT / 64);
    for (int ci = 0; ci < NN / MSPLIT / 64; ci++) {
        const int m0c = (ck0 + ci) * 64;
        __syncthreads();
        if (t < 64) scr[t] = g_crcp[b * NN + m0c + t];
        __syncthreads();

        // Stage P (128n x 64m): pure fp16 copy, swizzled
        const __half* sg = g_probs + ((size_t)b * NN + nblk) * NN + m0c;
#pragma unroll
        for (int i = 0; i < 4; i++) {
            int idx = i * 256 + t;
            int row = idx >> 3, c8 = idx & 7;
            uint4 raw = *(const uint4*)(sg + (size_t)row * NN + c8 * 8);
            uint32_t off = (uint32_t)(row * 128 + ((c8 ^ (row & 7)) << 4));
            *(uint4*)(smc + O_P + off) = raw;
        }
        // Stage V' (64m x 64d): rcp-prescale + fp16 hi/lo split, swizzled
        const float* vg = v + ((size_t)b * NN + m0c) * DD;
#pragma unroll
        for (int i = 0; i < 4; i++) {
            int idx = i * 256 + t;
            int row = idx >> 4, c4 = idx & 15;
            float4 v4 = *(const float4*)(vg + (size_t)row * DD + c4 * 4);
            float rs = scr[row];
            v4.x *= rs; v4.y *= rs; v4.z *= rs; v4.w *= rs;
            uint32_t h01, l01, h23, l23;
            split2h(v4.x, v4.y, h01, l01);
            split2h(v4.z, v4.w, h23, l23);
            uint32_t off = (uint32_t)(row * 128 + (((c4 >> 1) ^ (row & 7)) << 4) +
                                      ((c4 & 1) << 3));
            *(uint2*)(smc + O_VH + off) = make_uint2(h01, h23);
            *(uint2*)(smc + O_VL + off) = make_uint2(l01, l23);
        }
        __syncthreads();

#pragma unroll
        for (int pass = 0; pass < 2; pass++) {
            const uint32_t Ab = sb + O_P;
            const uint32_t Bb = sb + ((pass == 1) ? O_VL : O_VH);
#pragma unroll
            for (int ks = 0; ks < 4; ks++) {
                uint32_t a[2][4], bf[2][4];
#pragma unroll
                for (int fn = 0; fn < 2; fn++) {
                    int row = wn * 32 + fn * 16 + (l & 15);
                    int blk = ks * 2 + (l >> 4);
                    LDSM4(a[fn], Ab + row * 128 + ((blk ^ (row & 7)) << 4));
                }
#pragma unroll
                for (int p = 0; p < 2; p++) {
                    int row = ks * 16 + ((l >> 3) & 1) * 8 + (l & 7);
                    int blk = wd * 4 + p * 2 + (l >> 4);
                    LDSM4T(bf[p], Bb + row * 128 + ((blk ^ (row & 7)) << 4));
                }
#pragma unroll
                for (int fn = 0; fn < 2; fn++)
#pragma unroll
                    for (int fb = 0; fb < 4; fb++)
                        MMA_F16(c[fn][fb], a[fn], &bf[fb >> 1][(fb & 1) * 2]);
            }
        }
    }

    float* po = g_pout + (size_t)z * BB * NN * DD;
    const int g = l >> 2, tig = l & 3;
#pragma unroll
    for (int fn = 0; fn < 2; fn++) {
#pragma unroll
        for (int h = 0; h < 2; h++) {
            int n = nblk + wn * 32 + fn * 16 + g + h * 8;
#pragma unroll
            for (int fb = 0; fb < 4; fb++) {
                int d = wd * 32 + fb * 8 + tig * 2;
                float2 o = make_float2(c[fn][fb][h * 2], c[fn][fb][h * 2 + 1]);
                *(float2*)(po + ((size_t)b * NN + n) * DD + d) = o;
            }
        }
    }
}

// ============================================================================
// Kernel 4: reduce MSPLIT partials -> out (deterministic order)
// ============================================================================
__global__ void reduce_kernel(float* __restrict__ out) {
    size_t i = (size_t)blockIdx.x * 256 + threadIdx.x;   // float4 index
    const size_t stride = (size_t)BB * NN * DD / 4;
    float4 a = ((const float4*)g_pout)[i];
#pragma unroll
    for (int z = 1; z < MSPLIT; z++) {
        float4 p = ((const float4*)g_pout)[z * stride + i];
        a.x += p.x; a.y += p.y; a.z += p.z; a.w += p.w;
    }
    ((float4*)out)[i] = a;
}

// ============================================================================
extern "C" void kernel_launch(void* const* d_in, const int* in_sizes, int n_in,
                              void* d_out, int out_size) {
    const float* q = (const float*)d_in[0];
    const float* k = (const float*)d_in[1];
    const float* v = (const float*)d_in[2];
    const int* mask = (const int*)d_in[3];
    float* out = (float*)d_out;

    cudaFuncSetAttribute(scores_mma_kernel,
                         cudaFuncAttributeMaxDynamicSharedMemorySize, SC_SMEM);
    cudaFuncSetAttribute(out_mma_kernel,
                         cudaFuncAttributeMaxDynamicSharedMemorySize, O_SMEM);

    prep_kernel<<<2048, 256>>>(q, k);
    scores_mma_kernel<<<dim3(NN / 128, NN / 128, BB), 256, SC_SMEM>>>(mask);
    colstats2_kernel<<<dim3(NN / 256, BB), 256>>>();
    out_mma_kernel<<<dim3(NN / 128, BB, MSPLIT), 256, O_SMEM>>>(v);
    reduce_kernel<<<BB * NN * DD / 4 / 256, 256>>>(out);
}